// round 16
// baseline (speedup 1.0000x reference)
#include <cuda_runtime.h>
#include <cstdint>

#define TT   512
#define BB   128
#define CLSZ 8
#define NTHR 512
#define NGRP 8      // batch groups, 16 batches each

// ---------------- smem layout (float indices) ----------------
#define OFF_U    0          // [128 col][260 pad h] tf32        33280
#define OFF_HB   33280      // [2 parity][16 n][260 pad h]       8320
#define OFF_OUT  41600      // [2 parity][16 b][32 k]            1024
#define OFF_PRE  42624      // [2 kh][128 col][17 pad n]         4352
#define OFF_WX   46976      // [128 col][4 f]                     512
#define OFF_WB   47488      // [128 col]                          128
#define OFF_FW   47616      // [256 k][4 f]                      1024
#define OFF_FB   48640      // [4]                                  4
#define OFF_SX   48644      // [2 buf][16 b][4 f]                 128
#define OFF_FLAG 48772      // [8] int local step flags             8
#define SMEM_FLOATS 48780
#define SMEM_BYTES (SMEM_FLOATS * 4)

// cross-layer handoff: y of layer 0, [G][T][16 b][4] + flags [G][16 b]
__device__ float g_y1[NGRP * TT * 16 * 4];
__device__ int   g_yf[NGRP * 16];

typedef unsigned long long ull;

__device__ __forceinline__ uint32_t smem_u32(const void* p) {
    uint32_t a;
    asm("{ .reg .u64 t; cvta.to.shared.u64 t, %1; cvt.u32.u64 %0, t; }"
        : "=r"(a) : "l"(p));
    return a;
}
__device__ __forceinline__ void cluster_sync() {
    asm volatile("barrier.cluster.arrive.aligned;" ::: "memory");
    asm volatile("barrier.cluster.wait.aligned;" ::: "memory");
}
__device__ __forceinline__ float fsig(float x) {
    float e, r;
    asm("ex2.approx.f32 %0, %1;" : "=f"(e) : "f"(x * -1.4426950408889634f));
    asm("rcp.approx.f32 %0, %1;" : "=f"(r) : "f"(1.0f + e));
    return r;
}
__device__ __forceinline__ float ftanh(float x) {
    float e, r;
    asm("ex2.approx.f32 %0, %1;" : "=f"(e) : "f"(x * -2.8853900817779268f));
    asm("rcp.approx.f32 %0, %1;" : "=f"(r) : "f"(1.0f + e));
    return __fmaf_rn(2.0f, r, -1.0f);
}
__device__ __forceinline__ uint32_t f2tf32(float x) {
    uint32_t u;
    asm("cvt.rna.tf32.f32 %0, %1;" : "=r"(u) : "f"(x));
    return u;
}
__device__ __forceinline__ void flag_spin(uint32_t fa, int target) {
    int v;
    do {
        asm volatile("ld.volatile.shared.b32 %0, [%1];" : "=r"(v) : "r"(fa));
    } while (v < target);
}
__device__ __forceinline__ void mma_tf32(float& d0, float& d1, float& d2, float& d3,
                                         uint32_t a0, uint32_t a1, uint32_t a2, uint32_t a3,
                                         uint32_t b0, uint32_t b1) {
    asm("mma.sync.aligned.m16n8k8.row.col.f32.tf32.tf32.f32 "
        "{%0,%1,%2,%3},{%4,%5,%6,%7},{%8,%9},{%0,%1,%2,%3};"
        : "+f"(d0), "+f"(d1), "+f"(d2), "+f"(d3)
        : "r"(a0), "r"(a1), "r"(a2), "r"(a3), "r"(b0), "r"(b1));
}
__device__ __forceinline__ void gstore_release(int* p, int v) {
    asm volatile("st.release.gpu.global.b32 [%0], %1;" :: "l"(p), "r"(v) : "memory");
}
__device__ __forceinline__ int gload_acquire(const int* p) {
    int v;
    asm volatile("ld.acquire.gpu.global.b32 %0, [%1];" : "=r"(v) : "l"(p) : "memory");
    return v;
}

#define QNEG_MASK 0x284E

__global__ void __launch_bounds__(NTHR, 1) __cluster_dims__(CLSZ, 1, 1)
qlstm_kernel(const float* __restrict__ x,
             const float* __restrict__ Wxr, const float* __restrict__ Wxi,
             const float* __restrict__ Wxj, const float* __restrict__ Wxk,
             const float* __restrict__ Wxb,
             const float* __restrict__ Ur,  const float* __restrict__ Ui,
             const float* __restrict__ Uj,  const float* __restrict__ Uk,
             const float* __restrict__ fcw, const float* __restrict__ fcb,
             float* __restrict__ out)
{
    extern __shared__ float sm[];
    float* sU   = sm + OFF_U;
    float* sHB  = sm + OFF_HB;     // + parity*4160
    float* sOut = sm + OFF_OUT;    // + parity*512
    float* sPre = sm + OFF_PRE;    // + kh*2176
    float* sWx  = sm + OFF_WX;
    float* sWb  = sm + OFF_WB;
    float* sFW  = sm + OFF_FW;
    float* sFB  = sm + OFF_FB;
    float* sX   = sm + OFF_SX;     // + buf*64

    const int tid  = threadIdx.x;
    const int lane = tid & 31;
    const int wid  = tid >> 5;
    const int r    = blockIdx.x & 7;            // cluster rank
    const int lay  = (blockIdx.x >> 3) & 1;     // layer of this cluster
    const int G    = blockIdx.x >> 4;           // batch group (16 batches)
    const uint32_t sbase = smem_u32(sm);

    // MMA role (all 16 warps): ct 0..7, kh 0..1
    const int ct = wid & 7;
    const int kh = wid >> 3;
    const int mr = lane >> 2;
    const int mc = lane & 3;

    // act role (warps 0..7): cell = lane, batches b0,b1 (of 16)
    const int b0 = wid * 2;
    const int b1 = b0 + 1;

    // pull role (warps 8..15): source rank pj
    const int pj = wid - 8;

    // ---- one-time init ----
    if (tid < 8) ((int*)(sm + OFF_FLAG))[tid] = 0;
    __syncthreads();
    cluster_sync();

    // ---- gather U slice (tf32), sU[col][260 pad h], layer = lay ----
    for (int idx = tid; idx < 4 * 256 * 32; idx += NTHR) {
        int g   = idx >> 13;
        int rem = idx & 8191;
        int h   = rem >> 5;
        int kl  = rem & 31;
        int kg  = r * 32 + kl;
        int hb  = h >> 6, n = h & 63;
        int cb  = kg >> 6, m = kg & 63;
        int sel = hb ^ cb;
        float sgn = ((QNEG_MASK >> (cb * 4 + hb)) & 1) ? -1.0f : 1.0f;
        const float* cp = (sel == 0) ? Ur : (sel == 1) ? Ui : (sel == 2) ? Uj : Uk;
        float v = sgn * __ldg(&cp[((lay * 4 + g) * 64 + n) * 64 + m]);
        sU[(g * 32 + kl) * 260 + h] = __uint_as_float(f2tf32(v));
    }
    for (int idx = tid; idx < 512; idx += NTHR) {
        int g  = idx >> 7;
        int f  = (idx >> 5) & 3;
        int kl = idx & 31;
        int kg = r * 32 + kl;
        int cb = kg >> 6, m = kg & 63;
        int sel = f ^ cb;
        float sgn = ((QNEG_MASK >> (cb * 4 + f)) & 1) ? -1.0f : 1.0f;
        const float* cp = (sel == 0) ? Wxr : (sel == 1) ? Wxi : (sel == 2) ? Wxj : Wxk;
        sWx[(g * 32 + kl) * 4 + f] = sgn * __ldg(&cp[(lay * 4 + g) * 64 + m]);
    }
    for (int idx = tid; idx < 128; idx += NTHR) {
        int g = idx >> 5, kl = idx & 31;
        sWb[idx] = Wxb[(lay * 4 + g) * 256 + r * 32 + kl];
    }
    for (int idx = tid; idx < 1024; idx += NTHR)
        sFW[idx] = fcw[lay * 1024 + idx];
    if (tid < 4) sFB[tid] = fcb[lay * 4 + tid];
    // zero both h parity buffers (h_0 = 0)
    for (int i = tid; i < 2 * 4160; i += NTHR) sHB[i] = 0.0f;
    __syncthreads();

    // ---- preload this warp's U A-fragments into registers ----
    uint32_t Afr[16][4];
    {
        const int row0 = ct * 16 + mr;
        const int kb0  = kh * 128 + mc;
#pragma unroll
        for (int kt = 0; kt < 16; kt++) {
            int kb = kb0 + kt * 8;
            Afr[kt][0] = __float_as_uint(sU[row0 * 260 + kb]);
            Afr[kt][1] = __float_as_uint(sU[(row0 + 8) * 260 + kb]);
            Afr[kt][2] = __float_as_uint(sU[row0 * 260 + kb + 4]);
            Afr[kt][3] = __float_as_uint(sU[(row0 + 8) * 260 + kb + 4]);
        }
    }

    // ---- layer-1 prologue: fetch y1[0] into sX[0] ----
    if (lay == 1 && wid == 9) {
        if (lane < 16) {
            const int* fp = &g_yf[G * 16 + lane];
            while (gload_acquire(fp) < 1) { }
            float4 y = *(const float4*)&g_y1[((G * TT + 0) * 16 + lane) * 4];
            *(float4*)&sX[lane * 4] = y;
        }
        __syncwarp();
    }
    __syncthreads();

    float2 creg = make_float2(0.f, 0.f);

    for (int t = 0; t < TT; t++) {
        const int cur = t & 1;
        const int nxt = cur ^ 1;

        // act warps (layer 0): prefetch x early
        float4 xv0, xv1;
        if (wid < 8 && lay == 0) {
            const float4* xp = (const float4*)x;
            xv0 = __ldg(&xp[(G * 16 + b0) * TT + t]);
            xv1 = __ldg(&xp[(G * 16 + b1) * TT + t]);
        }

        // ---- MMA: two batch-half passes, each D[16c x 8n] over K=128 (kh) ----
#pragma unroll
        for (int H = 0; H < 2; H++) {
            float dA0 = 0.f, dA1 = 0.f, dA2 = 0.f, dA3 = 0.f;
            float dB0 = 0.f, dB1 = 0.f, dB2 = 0.f, dB3 = 0.f;
            const float* bp = sHB + cur * 4160 + (H * 8 + mr) * 260 + kh * 128 + mc;
#pragma unroll
            for (int kt = 0; kt < 8; kt++) {
                uint32_t bb0 = __float_as_uint(bp[kt * 8]);
                uint32_t bb1 = __float_as_uint(bp[kt * 8 + 4]);
                mma_tf32(dA0, dA1, dA2, dA3,
                         Afr[kt][0], Afr[kt][1], Afr[kt][2], Afr[kt][3], bb0, bb1);
            }
#pragma unroll
            for (int kt = 8; kt < 16; kt++) {
                uint32_t bb0 = __float_as_uint(bp[kt * 8]);
                uint32_t bb1 = __float_as_uint(bp[kt * 8 + 4]);
                mma_tf32(dB0, dB1, dB2, dB3,
                         Afr[kt][0], Afr[kt][1], Afr[kt][2], Afr[kt][3], bb0, bb1);
            }
            const int colA = ct * 16 + mr;
            const int nn   = H * 8 + mc * 2;
            float* p0 = sPre + kh * 2176 + colA * 17 + nn;
            float* p1 = sPre + kh * 2176 + (colA + 8) * 17 + nn;
            p0[0] = dA0 + dB0; p0[1] = dA1 + dB1;
            p1[0] = dA2 + dB2; p1[1] = dA3 + dB3;
        }
        __syncthreads();   // sPre complete

        if (wid < 8) {
            // ---- act: combine K-halves + gates + cell update ----
            if (lay == 1) {
                xv0 = *(const float4*)&sX[cur * 64 + b0 * 4];
                xv1 = *(const float4*)&sX[cur * 64 + b1 * 4];
            }
            float pre0[4], pre1[4];
#pragma unroll
            for (int g = 0; g < 4; g++) {
                int col = g * 32 + lane;
                float4 wx = *(const float4*)&sWx[col * 4];
                float wb  = sWb[col];
                float base0 = sPre[col * 17 + b0] + sPre[2176 + col * 17 + b0];
                float base1 = sPre[col * 17 + b1] + sPre[2176 + col * 17 + b1];
                pre0[g] = base0 + wb + xv0.x * wx.x + xv0.y * wx.y
                                     + xv0.z * wx.z + xv0.w * wx.w;
                pre1[g] = base1 + wb + xv1.x * wx.x + xv1.y * wx.y
                                     + xv1.z * wx.z + xv1.w * wx.w;
            }
            {
                float ft = fsig(pre0[0]), it = fsig(pre0[1]);
                float ot = fsig(pre0[2]), cc = ftanh(pre0[3]);
                float c = it * cc + ft * creg.x;
                creg.x = c;
                sOut[cur * 512 + b0 * 32 + lane] =
                    __uint_as_float(f2tf32(ot * ftanh(c)));
            }
            {
                float ft = fsig(pre1[0]), it = fsig(pre1[1]);
                float ot = fsig(pre1[2]), cc = ftanh(pre1[3]);
                float c = it * cc + ft * creg.y;
                creg.y = c;
                sOut[cur * 512 + b1 * 32 + lane] =
                    __uint_as_float(f2tf32(ot * ftanh(c)));
            }
            asm volatile("bar.sync 1, 256;" ::: "memory");   // drain sOut (act warps)
            if (tid == 0) {
                const int gs = t + 1;
                uint32_t fa = sbase + (OFF_FLAG + r) * 4;
#pragma unroll
                for (int j = 0; j < CLSZ; j++) {
                    uint32_t ra;
                    asm("mapa.shared::cluster.u32 %0, %1, %2;"
                        : "=r"(ra) : "r"(fa), "r"(j));
                    asm volatile("st.shared::cluster.b32 [%0], %1;"
                                 :: "r"(ra), "r"(gs) : "memory");
                }
            }
        } else {
            // ---- y warps (layer 0, per-step): y_{t-1} for batch 2r / 2r+1 ----
            if (lay == 0 && t > 0 && (wid == 12 || wid == 13)) {
                const int bb = 2 * r + (wid - 12);
                const float* hb = sHB + cur * 4160 + bb * 260;
                float s0 = 0.f, s1 = 0.f, s2 = 0.f, s3 = 0.f;
#pragma unroll
                for (int i = 0; i < 8; i++) {
                    int kk = lane + i * 32;
                    float hv = hb[kk];
                    float4 fw = *(const float4*)&sFW[kk * 4];
                    s0 += hv * fw.x; s1 += hv * fw.y;
                    s2 += hv * fw.z; s3 += hv * fw.w;
                }
#pragma unroll
                for (int m = 16; m >= 1; m >>= 1) {
                    s0 += __shfl_xor_sync(0xffffffffu, s0, m);
                    s1 += __shfl_xor_sync(0xffffffffu, s1, m);
                    s2 += __shfl_xor_sync(0xffffffffu, s2, m);
                    s3 += __shfl_xor_sync(0xffffffffu, s3, m);
                }
                if (lane == 0) {
                    s0 += sFB[0]; s1 += sFB[1]; s2 += sFB[2]; s3 += sFB[3];
                    float nn = s0*s0 + s1*s1 + s2*s2 + s3*s3;
                    float iv = 1.0f / fmaxf(sqrtf(nn), 1e-12f);
                    *(float4*)&g_y1[((G * TT + (t - 1)) * 16 + bb) * 4] =
                        make_float4(s0*iv, s1*iv, s2*iv, s3*iv);
                    gstore_release(&g_yf[G * 16 + bb], t);
                }
            }
            // ---- pull warp for rank pj ----
            if (lane == 0) flag_spin(sbase + (OFF_FLAG + pj) * 4, t + 1);
            __syncwarp();
#pragma unroll
            for (int q = 0; q < 8; q++) {
                int idx = lane + 32 * q;          // 0..255 b64 units
                int b   = idx >> 4;
                int ko  = (idx & 15) * 2;
                uint32_t so = sbase +
                    (uint32_t)(OFF_OUT + cur * 512 + b * 32 + ko) * 4;
                uint32_t ra;
                asm("mapa.shared::cluster.u32 %0, %1, %2;"
                    : "=r"(ra) : "r"(so), "r"(pj));
                ull v;
                asm volatile("ld.shared::cluster.b64 %0, [%1];"
                             : "=l"(v) : "r"(ra) : "memory");
                asm volatile("st.shared.b64 [%0], %1;"
                             :: "r"(sbase + (uint32_t)(OFF_HB + nxt * 4160 +
                                    b * 260 + pj * 32 + ko) * 4),
                                "l"(v) : "memory");
            }
            // ---- layer-1 prefetch y1[t+1] into sX[nxt] (self-lagging) ----
            if (lay == 1 && wid == 9 && t < TT - 1) {
                if (lane < 16) {
                    const int* fp = &g_yf[G * 16 + lane];
                    while (gload_acquire(fp) < t + 2) { }
                    float4 y = *(const float4*)&g_y1[((G * TT + t + 1) * 16 + lane) * 4];
                    *(float4*)&sX[nxt * 64 + lane * 4] = y;
                }
                __syncwarp();
            }
        }
        __syncthreads();   // sHB[nxt] = h_{t+1} complete
    } // t

    // ---- final y from h_T (state in parity 0 after t=511) ----
    if (wid == 12 || wid == 13) {
        const int bb = 2 * r + (wid - 12);
        const float* hb = sHB + 0 * 4160 + bb * 260;
        float s0 = 0.f, s1 = 0.f, s2 = 0.f, s3 = 0.f;
#pragma unroll
        for (int i = 0; i < 8; i++) {
            int kk = lane + i * 32;
            float hv = hb[kk];
            float4 fw = *(const float4*)&sFW[kk * 4];
            s0 += hv * fw.x; s1 += hv * fw.y;
            s2 += hv * fw.z; s3 += hv * fw.w;
        }
#pragma unroll
        for (int m = 16; m >= 1; m >>= 1) {
            s0 += __shfl_xor_sync(0xffffffffu, s0, m);
            s1 += __shfl_xor_sync(0xffffffffu, s1, m);
            s2 += __shfl_xor_sync(0xffffffffu, s2, m);
            s3 += __shfl_xor_sync(0xffffffffu, s3, m);
        }
        if (lane == 0) {
            s0 += sFB[0]; s1 += sFB[1]; s2 += sFB[2]; s3 += sFB[3];
            float nn = s0*s0 + s1*s1 + s2*s2 + s3*s3;
            float iv = 1.0f / fmaxf(sqrtf(nn), 1e-12f);
            if (lay == 0) {
                *(float4*)&g_y1[((G * TT + (TT - 1)) * 16 + bb) * 4] =
                    make_float4(s0*iv, s1*iv, s2*iv, s3*iv);
                gstore_release(&g_yf[G * 16 + bb], TT);
            } else {
                ((float4*)out)[G * 16 + bb] =
                    make_float4(s0*iv, s1*iv, s2*iv, s3*iv);
            }
        }
    }

    cluster_sync();   // no CTA exits while peers may still touch its SMEM
}

extern "C" void kernel_launch(void* const* d_in, const int* in_sizes, int n_in,
                              void* d_out, int out_size)
{
    (void)in_sizes; (void)n_in; (void)out_size;
    cudaFuncSetAttribute(qlstm_kernel,
                         cudaFuncAttributeMaxDynamicSharedMemorySize, SMEM_BYTES);
    qlstm_kernel<<<16 * CLSZ, NTHR, SMEM_BYTES>>>(
        (const float*)d_in[0],
        (const float*)d_in[1], (const float*)d_in[2],
        (const float*)d_in[3], (const float*)d_in[4],
        (const float*)d_in[5],
        (const float*)d_in[6], (const float*)d_in[7],
        (const float*)d_in[8], (const float*)d_in[9],
        (const float*)d_in[10], (const float*)d_in[11],
        (float*)d_out);
}

// round 17
// speedup vs baseline: 1.8080x; 1.8080x over previous
#include <cuda_runtime.h>
#include <cuda_bf16.h>
#include <cstdint>

#define LL   2
#define TT   512
#define BB   128
#define CLSZ 8
#define NCL  16
#define NTHR 512

// ---------------- smem layout (float-word indices) ----------------
#define OFF_U    0          // [128 col][132 words] bf16x2      16896
#define OFF_HB   16896      // [2 parity][8 n][132 words] bf16   2112
#define OFF_OUT  19008      // [2 parity][8 b][16 words] bf16     256
#define OFF_PRE  19264      // [2 kh][128 col][9 pad n] fp32     2304
#define OFF_WX   21568      // [128 col][4 f]                     512
#define OFF_WB   22080      // [128 col]                          128
#define OFF_FW   22208      // [256 k][4 f]                      1024
#define OFF_FB   23232      // [4]                                  4
#define OFF_FLAG 23236      // [8] int step flags                   8
#define SMEM_FLOATS 23244
#define SMEM_BYTES (SMEM_FLOATS * 4)

// layer-1 output scratch, TRANSPOSED: [B][T][4]
__device__ float g_y1[BB * TT * 4];

typedef unsigned long long ull;

__device__ __forceinline__ uint32_t smem_u32(const void* p) {
    uint32_t a;
    asm("{ .reg .u64 t; cvta.to.shared.u64 t, %1; cvt.u32.u64 %0, t; }"
        : "=r"(a) : "l"(p));
    return a;
}
__device__ __forceinline__ void cluster_sync() {
    asm volatile("barrier.cluster.arrive.aligned;" ::: "memory");
    asm volatile("barrier.cluster.wait.aligned;" ::: "memory");
}
__device__ __forceinline__ float fsig(float x) {
    float e, r;
    asm("ex2.approx.f32 %0, %1;" : "=f"(e) : "f"(x * -1.4426950408889634f));
    asm("rcp.approx.f32 %0, %1;" : "=f"(r) : "f"(1.0f + e));
    return r;
}
__device__ __forceinline__ float ftanh(float x) {
    float e, r;
    asm("ex2.approx.f32 %0, %1;" : "=f"(e) : "f"(x * -2.8853900817779268f));
    asm("rcp.approx.f32 %0, %1;" : "=f"(r) : "f"(1.0f + e));
    return __fmaf_rn(2.0f, r, -1.0f);
}
// pack two fp32 into bf16x2 word: lo = v0 (even h), hi = v1 (odd h)
__device__ __forceinline__ uint32_t pack_bf16x2(float v0, float v1) {
    uint32_t w;
    asm("cvt.rn.bf16x2.f32 %0, %1, %2;" : "=r"(w) : "f"(v1), "f"(v0));
    return w;
}
__device__ __forceinline__ void flag_spin(uint32_t fa, int target) {
    int v;
    do {
        asm volatile("ld.volatile.shared.b32 %0, [%1];" : "=r"(v) : "r"(fa));
    } while (v < target);
}
__device__ __forceinline__ void mma_bf16(float& d0, float& d1, float& d2, float& d3,
                                         uint32_t a0, uint32_t a1, uint32_t a2, uint32_t a3,
                                         uint32_t b0, uint32_t b1) {
    asm("mma.sync.aligned.m16n8k16.row.col.f32.bf16.bf16.f32 "
        "{%0,%1,%2,%3},{%4,%5,%6,%7},{%8,%9},{%0,%1,%2,%3};"
        : "+f"(d0), "+f"(d1), "+f"(d2), "+f"(d3)
        : "r"(a0), "r"(a1), "r"(a2), "r"(a3), "r"(b0), "r"(b1));
}

#define QNEG_MASK 0x284E

__global__ void __launch_bounds__(NTHR, 1) __cluster_dims__(CLSZ, 1, 1)
qlstm_kernel(const float* __restrict__ x,
             const float* __restrict__ Wxr, const float* __restrict__ Wxi,
             const float* __restrict__ Wxj, const float* __restrict__ Wxk,
             const float* __restrict__ Wxb,
             const float* __restrict__ Ur,  const float* __restrict__ Ui,
             const float* __restrict__ Uj,  const float* __restrict__ Uk,
             const float* __restrict__ fcw, const float* __restrict__ fcb,
             float* __restrict__ out)
{
    extern __shared__ float sm[];
    uint32_t* sU16 = (uint32_t*)(sm + OFF_U);     // [col][132 words]
    uint32_t* sHBw = (uint32_t*)(sm + OFF_HB);    // + parity*1056
    __nv_bfloat16* sOutH = (__nv_bfloat16*)(sm + OFF_OUT);  // halfword idx
    float* sPre = sm + OFF_PRE;
    float* sWx  = sm + OFF_WX;
    float* sWb  = sm + OFF_WB;
    float* sFW  = sm + OFF_FW;
    float* sFB  = sm + OFF_FB;

    const int tid  = threadIdx.x;
    const int lane = tid & 31;
    const int wid  = tid >> 5;
    const int r    = blockIdx.x & 7;
    const int cid  = blockIdx.x >> 3;
    const uint32_t sbase = smem_u32(sm);

    // mma role (all 16 warps): warp = (col-tile ct 0..7, K-half kh 0..1)
    const int ct = wid & 7;
    const int kh = wid >> 3;
    const int mr = lane >> 2;
    const int mc = lane & 3;

    // act role (warps 0..3): cell k = lane, batches b0,b1
    const int k  = lane;
    const int b0 = wid * 2;
    const int b1 = b0 + 1;

    // pull role: thread handles rank pj, (b, word-pair wi)
    const int pj  = tid >> 6;          // 0..7 (warp-uniform pairs)
    const int rem = tid & 63;
    const int pb  = rem >> 3;          // batch 0..7
    const int wi  = rem & 7;           // b64 index (2 words)
    const uint32_t flagA = sbase + (OFF_FLAG + pj) * 4;

    // ---- one-time init ----
    if (tid < 8) ((int*)(sm + OFF_FLAG))[tid] = 0;
    __syncthreads();
    cluster_sync();

    float2 creg;

    for (int l = 0; l < LL; l++) {
        __syncthreads();

        // ---- gather U slice as bf16x2 words: sU16[col*132 + w], w=h/2 ----
        for (int idx = tid; idx < 128 * 128; idx += NTHR) {
            int col = idx >> 7;            // 0..127  (= g*32 + kl)
            int w   = idx & 127;           // word: h = 2w, 2w+1
            int g   = col >> 5;
            int kl  = col & 31;
            int kg  = r * 32 + kl;
            int hb  = w >> 5;              // (2w)>>6
            int n0  = (2 * w) & 63;
            int cb  = kg >> 6, m = kg & 63;
            int sel = hb ^ cb;
            float sgn = ((QNEG_MASK >> (cb * 4 + hb)) & 1) ? -1.0f : 1.0f;
            const float* cp = (sel == 0) ? Ur : (sel == 1) ? Ui : (sel == 2) ? Uj : Uk;
            const float* bp2 = &cp[((l * 4 + g) * 64 + n0) * 64 + m];
            float v0 = sgn * __ldg(bp2);
            float v1 = sgn * __ldg(bp2 + 64);
            sU16[col * 132 + w] = pack_bf16x2(v0, v1);
        }
        for (int idx = tid; idx < 512; idx += NTHR) {
            int g  = idx >> 7;
            int f  = (idx >> 5) & 3;
            int kl = idx & 31;
            int kg = r * 32 + kl;
            int cb = kg >> 6, m = kg & 63;
            int sel = f ^ cb;
            float sgn = ((QNEG_MASK >> (cb * 4 + f)) & 1) ? -1.0f : 1.0f;
            const float* cp = (sel == 0) ? Wxr : (sel == 1) ? Wxi : (sel == 2) ? Wxj : Wxk;
            sWx[(g * 32 + kl) * 4 + f] = sgn * __ldg(&cp[(l * 4 + g) * 64 + m]);
        }
        for (int idx = tid; idx < 128; idx += NTHR) {
            int g = idx >> 5, kl = idx & 31;
            sWb[idx] = Wxb[(l * 4 + g) * 256 + r * 32 + kl];
        }
        for (int idx = tid; idx < 1024; idx += NTHR)
            sFW[idx] = fcw[l * 1024 + idx];
        if (tid < 4) sFB[tid] = fcb[l * 4 + tid];
        // zero both h parity buffers (h_0 = 0)
        for (int i = tid; i < 2 * 1056; i += NTHR) sHBw[i] = 0u;
        creg = make_float2(0.0f, 0.0f);
        __syncthreads();

        // ---- preload this warp's U A-fragments (bf16x2) into registers ----
        uint32_t Afr[8][4];
        {
            const uint32_t* up = sU16 + (ct * 16 + mr) * 132 + kh * 64 + mc;
#pragma unroll
            for (int kt = 0; kt < 8; kt++) {
                Afr[kt][0] = up[kt * 8];
                Afr[kt][1] = up[8 * 132 + kt * 8];
                Afr[kt][2] = up[kt * 8 + 4];
                Afr[kt][3] = up[8 * 132 + kt * 8 + 4];
            }
        }

        const float4* xp = (const float4*)((l == 0) ? x : g_y1);  // [B][T][4]

        for (int t = 0; t < TT; t++) {
            const int cur = t & 1;
            const int nxt = cur ^ 1;

            // ---- act warps: prefetch x early (hidden under MMA) ----
            float4 xv0, xv1;
            if (wid < 4) {
                xv0 = __ldg(&xp[(cid * 8 + b0) * TT + t]);
                xv1 = __ldg(&xp[(cid * 8 + b1) * TT + t]);
            }

            // ---- y-warp: y_{t-1} = norm(fco(h_t)) (layer 0; overlaps GEMM) ----
            if (l == 0 && wid == 15 && t > 0) {
                const __nv_bfloat16* hb = (const __nv_bfloat16*)sHBw +
                                          cur * 2112 + r * 264;
                float s0 = 0.f, s1 = 0.f, s2 = 0.f, s3 = 0.f;
#pragma unroll
                for (int i = 0; i < 8; i++) {
                    int kk = lane + i * 32;
                    float hv = __bfloat162float(hb[kk]);
                    float4 fw = *(const float4*)&sFW[kk * 4];
                    s0 += hv * fw.x; s1 += hv * fw.y;
                    s2 += hv * fw.z; s3 += hv * fw.w;
                }
#pragma unroll
                for (int m = 16; m >= 1; m >>= 1) {
                    s0 += __shfl_xor_sync(0xffffffffu, s0, m);
                    s1 += __shfl_xor_sync(0xffffffffu, s1, m);
                    s2 += __shfl_xor_sync(0xffffffffu, s2, m);
                    s3 += __shfl_xor_sync(0xffffffffu, s3, m);
                }
                if (lane == 0) {
                    s0 += sFB[0]; s1 += sFB[1]; s2 += sFB[2]; s3 += sFB[3];
                    float nn = s0*s0 + s1*s1 + s2*s2 + s3*s3;
                    float iv = 1.0f / fmaxf(sqrtf(nn), 1e-12f);
                    ((float4*)g_y1)[(cid * 8 + r) * TT + (t - 1)] =
                        make_float4(s0*iv, s1*iv, s2*iv, s3*iv);
                }
            }

            // ---- tensor GEMM: D[16c x 8b] += U^T tile @ h_t (bf16, K=128/warp) ----
            {
                float dA0 = 0.f, dA1 = 0.f, dA2 = 0.f, dA3 = 0.f;
                float dB0 = 0.f, dB1 = 0.f, dB2 = 0.f, dB3 = 0.f;
                const uint32_t* bp = sHBw + cur * 1056 + mr * 132 + kh * 64 + mc;
#pragma unroll
                for (int kt = 0; kt < 4; kt++) {
                    uint32_t bb0 = bp[kt * 8];
                    uint32_t bb1 = bp[kt * 8 + 4];
                    mma_bf16(dA0, dA1, dA2, dA3,
                             Afr[kt][0], Afr[kt][1], Afr[kt][2], Afr[kt][3], bb0, bb1);
                }
#pragma unroll
                for (int kt = 4; kt < 8; kt++) {
                    uint32_t bb0 = bp[kt * 8];
                    uint32_t bb1 = bp[kt * 8 + 4];
                    mma_bf16(dB0, dB1, dB2, dB3,
                             Afr[kt][0], Afr[kt][1], Afr[kt][2], Afr[kt][3], bb0, bb1);
                }
                const int colA = ct * 16 + mr;
                const int nn   = mc * 2;
                float* p0 = sPre + kh * 1152 + colA * 9 + nn;
                float* p1 = sPre + kh * 1152 + (colA + 8) * 9 + nn;
                p0[0] = dA0 + dB0; p0[1] = dA1 + dB1;
                p1[0] = dA2 + dB2; p1[1] = dA3 + dB3;
            }
            __syncthreads();   // sPre complete

            // ---- combine + activations + cell update (tid<128) ----
            if (tid < 128) {
                float pre0[4], pre1[4];
#pragma unroll
                for (int g = 0; g < 4; g++) {
                    int col = g * 32 + k;
                    float4 wx = *(const float4*)&sWx[col * 4];
                    float wb  = sWb[col];
                    float base0 = sPre[col * 9 + b0] + sPre[1152 + col * 9 + b0];
                    float base1 = sPre[col * 9 + b1] + sPre[1152 + col * 9 + b1];
                    pre0[g] = base0 + wb + xv0.x * wx.x + xv0.y * wx.y
                                         + xv0.z * wx.z + xv0.w * wx.w;
                    pre1[g] = base1 + wb + xv1.x * wx.x + xv1.y * wx.y
                                         + xv1.z * wx.z + xv1.w * wx.w;
                }
                {
                    float ft = fsig(pre0[0]), it = fsig(pre0[1]);
                    float ot = fsig(pre0[2]), cc = ftanh(pre0[3]);
                    float c = it * cc + ft * creg.x;
                    creg.x = c;
                    sOutH[cur * 256 + b0 * 32 + k] = __float2bfloat16(ot * ftanh(c));
                }
                {
                    float ft = fsig(pre1[0]), it = fsig(pre1[1]);
                    float ot = fsig(pre1[2]), cc = ftanh(pre1[3]);
                    float c = it * cc + ft * creg.y;
                    creg.y = c;
                    sOutH[cur * 256 + b1 * 32 + k] = __float2bfloat16(ot * ftanh(c));
                }
            }
            __syncthreads();   // sOut committed (BAR drains STS)

            // ---- publish step flag to all 8 ranks ----
            const int gs = l * TT + t + 1;
            if (tid == 0) {
                uint32_t fa = sbase + (OFF_FLAG + r) * 4;
#pragma unroll
                for (int j = 0; j < CLSZ; j++) {
                    uint32_t ra;
                    asm("mapa.shared::cluster.u32 %0, %1, %2;"
                        : "=r"(ra) : "r"(fa), "r"(j));
                    asm volatile("st.shared::cluster.b32 [%0], %1;"
                                 :: "r"(ra), "r"(gs) : "memory");
                }
            }

            // ---- spin on the source rank this thread pulls from, then pull ----
            flag_spin(flagA, gs);
            {
                const uint32_t so = sbase +
                    (uint32_t)(OFF_OUT + cur * 128 + pb * 16 + wi * 2) * 4;
                uint32_t ra; ull v;
                asm("mapa.shared::cluster.u32 %0, %1, %2;"
                    : "=r"(ra) : "r"(so), "r"(pj));
                asm volatile("ld.shared::cluster.b64 %0, [%1];"
                             : "=l"(v) : "r"(ra) : "memory");
                asm volatile("st.shared.b64 [%0], %1;"
                             :: "r"(sbase + (uint32_t)(OFF_HB + nxt * 1056 +
                                    pb * 132 + pj * 16 + wi * 2) * 4),
                                "l"(v) : "memory");
            }
            __syncthreads();  // sHB[nxt] = h_{t+1} complete
        } // t

        // ---- final y from h_T (parity 0 after t=511) ----
        if (wid == 15) {
            const __nv_bfloat16* hb = (const __nv_bfloat16*)sHBw + r * 264;
            float s0 = 0.f, s1 = 0.f, s2 = 0.f, s3 = 0.f;
#pragma unroll
            for (int i = 0; i < 8; i++) {
                int kk = lane + i * 32;
                float hv = __bfloat162float(hb[kk]);
                float4 fw = *(const float4*)&sFW[kk * 4];
                s0 += hv * fw.x; s1 += hv * fw.y;
                s2 += hv * fw.z; s3 += hv * fw.w;
            }
#pragma unroll
            for (int m = 16; m >= 1; m >>= 1) {
                s0 += __shfl_xor_sync(0xffffffffu, s0, m);
                s1 += __shfl_xor_sync(0xffffffffu, s1, m);
                s2 += __shfl_xor_sync(0xffffffffu, s2, m);
                s3 += __shfl_xor_sync(0xffffffffu, s3, m);
            }
            if (lane == 0) {
                s0 += sFB[0]; s1 += sFB[1]; s2 += sFB[2]; s3 += sFB[3];
                float nn = s0*s0 + s1*s1 + s2*s2 + s3*s3;
                float iv = 1.0f / fmaxf(sqrtf(nn), 1e-12f);
                if (l == 0) {
                    ((float4*)g_y1)[(cid * 8 + r) * TT + (TT - 1)] =
                        make_float4(s0*iv, s1*iv, s2*iv, s3*iv);
                } else {
                    ((float4*)out)[cid * 8 + r] =
                        make_float4(s0*iv, s1*iv, s2*iv, s3*iv);
                }
            }
        }
        cluster_sync();   // g_y1 visible cluster-wide before next layer
    } // l

    cluster_sync();   // no CTA exits while peers may still touch its SMEM
}

extern "C" void kernel_launch(void* const* d_in, const int* in_sizes, int n_in,
                              void* d_out, int out_size)
{
    (void)in_sizes; (void)n_in; (void)out_size;
    cudaFuncSetAttribute(qlstm_kernel,
                         cudaFuncAttributeMaxDynamicSharedMemorySize, SMEM_BYTES);
    qlstm_kernel<<<NCL * CLSZ, NTHR, SMEM_BYTES>>>(
        (const float*)d_in[0],
        (const float*)d_in[1], (const float*)d_in[2],
        (const float*)d_in[3], (const float*)d_in[4],
        (const float*)d_in[5],
        (const float*)d_in[6], (const float*)d_in[7],
        (const float*)d_in[8], (const float*)d_in[9],
        (const float*)d_in[10], (const float*)d_in[11],
        (float*)d_out);
}